// round 1
// baseline (speedup 1.0000x reference)
#include <cuda_runtime.h>
#include <cuda_bf16.h>

// FeatureRecalibration3D: x[2,64,64,96,96] fp32
//   s = depthwise_conv3x3x3(x, pad=1)         (never materialized!)
//   z = mean(s, DHW)                          -> [B,C]
//   h = leakyrelu(fc1 z + b1); g = sigmoid(fc2 h + b2)
//   out = x * g[b,c]
//
// Sum-of-conv trick: contribution of each x element to z depends only on
// its (first/mid/last) category per axis -> 27-entry coefficient table
// per channel, precomputed from the 27 depthwise weights.

#define B_  2
#define C_  64
#define D_  64
#define H_  96
#define W_  96
#define HW_ (H_ * W_)            // 9216
#define DHW_ (D_ * H_ * W_)      // 589824
#define NBC (B_ * C_)            // 128
#define NEG_SLOPE 0.01f

#define RED_SPLIT 16             // blocks per (b,c) slab in reduction
#define RED_THREADS 256
// per block: DHW_/RED_SPLIT = 36864 elems = 9216 float4; /256 thr = 36 f4/thr
#define RED_F4_PER_BLOCK (DHW_ / RED_SPLIT / 4)   // 9216
#define RED_ITERS (RED_F4_PER_BLOCK / RED_THREADS) // 36

#define SC_SPLIT 36              // blocks per slab in scale pass
#define SC_THREADS 256
#define SC_F4_PER_BLOCK (DHW_ / SC_SPLIT / 4)     // 4096
#define SC_ITERS (SC_F4_PER_BLOCK / SC_THREADS)   // 16

__device__ float g_partials[NBC * RED_SPLIT];
__device__ float g_gate[NBC];

// kd-range per category: first -> {0,1}, mid -> {0,1,2}, last -> {1,2}
__device__ __forceinline__ int k_lo(int cat) { return (cat == 2) ? 1 : 0; }
__device__ __forceinline__ int k_hi(int cat) { return (cat == 0) ? 1 : 2; }

// ---------------- Pass A: weighted reduction over x ----------------
__global__ __launch_bounds__(RED_THREADS)
void reduce_kernel(const float* __restrict__ x,
                   const float* __restrict__ dw_w) {
    const int slab = blockIdx.x / RED_SPLIT;   // bc index, 0..127
    const int part = blockIdx.x % RED_SPLIT;
    const int c = slab & (C_ - 1);
    const int tid = threadIdx.x;

    __shared__ float A_s[27];
    __shared__ float red_s[RED_THREADS];

    // Build 27-entry category-coefficient table for this channel.
    if (tid < 27) {
        const int cd = tid / 9, ch = (tid / 3) % 3, cw = tid % 3;
        const float* wc = dw_w + c * 27;
        float a = 0.f;
        for (int kd = k_lo(cd); kd <= k_hi(cd); ++kd)
            for (int kh = k_lo(ch); kh <= k_hi(ch); ++kh)
                for (int kw = k_lo(cw); kw <= k_hi(cw); ++kw)
                    a += wc[kd * 9 + kh * 3 + kw];
        A_s[tid] = a;
    }
    __syncthreads();

    const float4* x4 = (const float4*)(x + (size_t)slab * DHW_);
    const int base4 = part * RED_F4_PER_BLOCK;

    float acc = 0.f;
#pragma unroll 4
    for (int it = 0; it < RED_ITERS; ++it) {
        const int idx4 = base4 + it * RED_THREADS + tid;
        const float4 v = __ldg(&x4[idx4]);
        const int i = idx4 * 4;
        const int d = i / HW_;
        const int rem = i - d * HW_;
        const int h = rem / W_;
        const int w = rem - h * W_;
        const int cd = (d == 0) ? 0 : ((d == D_ - 1) ? 2 : 1);
        const int ch = (h == 0) ? 0 : ((h == H_ - 1) ? 2 : 1);
        // w is a multiple of 4; only lane0 can be w==0, only lane3 can be 95
        const int cw0 = (w == 0) ? 0 : 1;
        const int cw3 = (w + 3 == W_ - 1) ? 2 : 1;
        const int cb = cd * 9 + ch * 3;
        acc += v.x * A_s[cb + cw0] + v.y * A_s[cb + 1]
             + v.z * A_s[cb + 1]   + v.w * A_s[cb + cw3];
    }

    red_s[tid] = acc;
    __syncthreads();
    for (int s = RED_THREADS / 2; s >= 32; s >>= 1) {
        if (tid < s) red_s[tid] += red_s[tid + s];
        __syncthreads();
    }
    if (tid < 32) {
        float v = red_s[tid];
#pragma unroll
        for (int o = 16; o > 0; o >>= 1)
            v += __shfl_down_sync(0xFFFFFFFFu, v, o);
        if (tid == 0) g_partials[slab * RED_SPLIT + part] = v;
    }
}

// ---------------- Pass B: finalize z + MLP + sigmoid gate ----------------
__global__ __launch_bounds__(128)
void mlp_kernel(const float* __restrict__ fc1_w,
                const float* __restrict__ fc1_b,
                const float* __restrict__ fc2_w,
                const float* __restrict__ fc2_b) {
    const int tid = threadIdx.x;  // 0..127 -> bc
    __shared__ float z_s[NBC];
    __shared__ float h_s[B_ * 8];

    float s = 0.f;
#pragma unroll
    for (int p = 0; p < RED_SPLIT; ++p)
        s += g_partials[tid * RED_SPLIT + p];
    z_s[tid] = s * (1.0f / (float)DHW_);
    __syncthreads();

    if (tid < B_ * 8) {
        const int b = tid / 8, i = tid % 8;
        float h = fc1_b[i];
        for (int c = 0; c < C_; ++c)
            h += z_s[b * C_ + c] * fc1_w[i * C_ + c];
        h_s[tid] = (h >= 0.f) ? h : NEG_SLOPE * h;
    }
    __syncthreads();

    const int b = tid / C_, c = tid % C_;
    float g = fc2_b[c];
#pragma unroll
    for (int i = 0; i < 8; ++i)
        g += h_s[b * 8 + i] * fc2_w[c * 8 + i];
    g_gate[tid] = 1.0f / (1.0f + __expf(-g));
}

// ---------------- Pass C: out = x * gate[b,c] ----------------
__global__ __launch_bounds__(SC_THREADS)
void scale_kernel(const float* __restrict__ x, float* __restrict__ out) {
    const int slab = blockIdx.x / SC_SPLIT;
    const int sub  = blockIdx.x % SC_SPLIT;
    const float g = g_gate[slab];

    const size_t base4 = (size_t)slab * (DHW_ / 4) + (size_t)sub * SC_F4_PER_BLOCK;
    const float4* x4 = (const float4*)x + base4;
    float4* o4 = (float4*)out + base4;
    const int tid = threadIdx.x;

#pragma unroll
    for (int it = 0; it < SC_ITERS; ++it) {
        const int idx = it * SC_THREADS + tid;
        float4 v = __ldg(&x4[idx]);
        v.x *= g; v.y *= g; v.z *= g; v.w *= g;
        o4[idx] = v;
    }
}

extern "C" void kernel_launch(void* const* d_in, const int* in_sizes, int n_in,
                              void* d_out, int out_size) {
    const float* x     = (const float*)d_in[0];
    const float* dw_w  = (const float*)d_in[1];
    const float* fc1_w = (const float*)d_in[2];
    const float* fc1_b = (const float*)d_in[3];
    const float* fc2_w = (const float*)d_in[4];
    const float* fc2_b = (const float*)d_in[5];
    float* out = (float*)d_out;

    reduce_kernel<<<NBC * RED_SPLIT, RED_THREADS>>>(x, dw_w);
    mlp_kernel<<<1, 128>>>(fc1_w, fc1_b, fc2_w, fc2_b);
    scale_kernel<<<NBC * SC_SPLIT, SC_THREADS>>>(x, out);
}